// round 12
// baseline (speedup 1.0000x reference)
#include <cuda_runtime.h>
#include <cuda_bf16.h>
#include <cstdint>
#include <cmath>

// ---------------------------------------------------------------------------
// WeightedRankNet R12: sweep (DRAM-bound, idle ALU) additionally computes the
// threefry freshness term fr[e] = max(0,u)*frw for all elements (coalesced
// 4 MB store) while streaming the table. It also packs per-doc
// (PG:f32, tf:bf16, dl:bf16) = 8B/doc + col16 partials.
// Gather (PDL): idx pre-load, griddep sync, L2 re-prime of the 8 MB table,
// per-block avg fold, then random 8B loads (L2 hits) + sequential fr loads.
// Threefry-2x32-20, key=(0,1), partitionable: bits = out0 ^ out1.
// ---------------------------------------------------------------------------

#define N_FEAT        136
#define COL_DOCLEN    14
#define COL_WHOLE_LEN 16
#define COL_TF        24
#define COL_INLINK    127
#define COL_OUTLINK   128
#define COL_PAGERANK  129

#define TPB        256
#define SUM_BLOCKS 1024
#define MAX_DOCS   (1 << 20)
#define MAX_BATCH  (1 << 20)
#define EPT        4

// word x = PG (f32 bits); word y = bf16x2(tf, dl)
__device__ uint2 g_packed[MAX_DOCS];       // 8 MB
__device__ float g_fr[MAX_BATCH];          // 4 MB: u*frw per element
__device__ float g_partials[SUM_BLOCKS];

// ---- Threefry-2x32 -------------------------------------------------------------
__device__ __forceinline__ uint32_t rotl32(uint32_t x, uint32_t r) {
    return __funnelshift_l(x, x, r);
}

__device__ __forceinline__ uint32_t threefry_bits(uint32_t ctr) {
    uint32_t x0 = 0u;
    uint32_t x1 = ctr;
    const uint32_t ks0 = 0u, ks1 = 1u, ks2 = 0x1BD11BDBu;
    x0 += ks0; x1 += ks1;
#define TF_R(r) { x0 += x1; x1 = rotl32(x1, (r)); x1 ^= x0; }
    TF_R(13) TF_R(15) TF_R(26) TF_R(6)
    x0 += ks1; x1 += ks2 + 1u;
    TF_R(17) TF_R(29) TF_R(16) TF_R(24)
    x0 += ks2; x1 += ks0 + 2u;
    TF_R(13) TF_R(15) TF_R(26) TF_R(6)
    x0 += ks0; x1 += ks1 + 3u;
    TF_R(17) TF_R(29) TF_R(16) TF_R(24)
    x0 += ks1; x1 += ks2 + 4u;
    TF_R(13) TF_R(15) TF_R(26) TF_R(6)
    x0 += ks2; x1 += ks0 + 5u;
#undef TF_R
    return x0 ^ x1;
}

// ---- 1) sweep: pack (PG, tf, dl) + col16 partials + threefry fr ----------------
__global__ void __launch_bounds__(TPB)
sweep_kernel(const float* __restrict__ gf,
             const float* __restrict__ s_pr,
             const float* __restrict__ s_in,
             const float* __restrict__ s_out,
             const float* __restrict__ s_fr,
             int n_docs, int batch)
{
    cudaTriggerProgrammaticLaunchCompletion();

    const int tid  = blockIdx.x * blockDim.x + threadIdx.x;
    const int S    = gridDim.x * blockDim.x;
    const int step = 4 * S;

    const float prw = __ldg(s_pr);
    const float inw = __ldg(s_in);
    const float otw = __ldg(s_out);
    const float frw = __ldg(s_fr);

    float csum = 0.0f;

    for (int base = tid; base < n_docs; base += step) {
        int  r[4];
        bool v[4];
        #pragma unroll
        for (int k = 0; k < 4; k++) {
            int rr = base + k * S;
            v[k] = (rr < n_docs);
            r[k] = v[k] ? rr : (n_docs - 1);
        }

        // issue all 24 loads back-to-back
        float dl[4], c16[4], tf[4], inl[4];
        float2 op[4];
        #pragma unroll
        for (int k = 0; k < 4; k++) {
            const float* row = gf + (long long)r[k] * N_FEAT;
            dl[k]  = __ldcs(row + COL_DOCLEN);
            c16[k] = __ldcs(row + COL_WHOLE_LEN);
            tf[k]  = __ldcs(row + COL_TF);
            inl[k] = __ldcs(row + COL_INLINK);
            op[k]  = __ldcs(reinterpret_cast<const float2*>(row + COL_OUTLINK));
        }

        // threefry for 4 elements rides under the load latency (idle ALU)
        #pragma unroll
        for (int k = 0; k < 4; k++) {
            int e = base + k * S;
            if (e < batch) {
                uint32_t bits = threefry_bits((uint32_t)e);
                float u = __uint_as_float((bits >> 9) | 0x3f800000u) - 1.0f;
                g_fr[e] = fmaxf(0.0f, u) * frw;
            }
        }

        #pragma unroll
        for (int k = 0; k < 4; k++) {
            if (!v[k]) break;
            csum += c16[k];
            float PG = prw * op[k].y + inw * inl[k] + otw * op[k].x;
            __nv_bfloat162 td = __floats2bfloat162_rn(tf[k], dl[k]);
            uint2 pk;
            pk.x = __float_as_uint(PG);
            pk.y = *reinterpret_cast<uint32_t*>(&td);
            g_packed[r[k]] = pk;
        }
    }

    // handle batch > n_docs leftovers (not hit here: batch == n_docs == 1M)
    for (int e = n_docs + tid; e < batch; e += S) {
        uint32_t bits = threefry_bits((uint32_t)e);
        float u = __uint_as_float((bits >> 9) | 0x3f800000u) - 1.0f;
        g_fr[e] = fmaxf(0.0f, u) * frw;
    }

    __shared__ float sd[TPB];
    sd[threadIdx.x] = csum;
    __syncthreads();
    for (int k = TPB / 2; k > 0; k >>= 1) {
        if (threadIdx.x < k) sd[threadIdx.x] += sd[threadIdx.x + k];
        __syncthreads();
    }
    if (threadIdx.x == 0) g_partials[blockIdx.x] = sd[0];
}

// ---- 2) gather (PDL secondary) ---------------------------------------------------
__global__ void __launch_bounds__(TPB)
gather_kernel(const int* __restrict__ idxs,
              const float* __restrict__ s_k1,
              const float* __restrict__ s_b,
              const float* __restrict__ s_bw,
              float* __restrict__ out,
              int batch, int n_docs, float idf)
{
    const int tid      = blockIdx.x * blockDim.x + threadIdx.x;
    const int nthreads = gridDim.x * blockDim.x;
    const int base     = tid * EPT;
    const int t        = threadIdx.x;

    // ---------- pre-wait work: independent of the sweep ----------
    int idx[EPT];
    const bool full = (base + EPT - 1 < batch);
    if (full) {
        int4 iv = *reinterpret_cast<const int4*>(idxs + base);
        idx[0] = iv.x; idx[1] = iv.y; idx[2] = iv.z; idx[3] = iv.w;
    } else if (base < batch) {
        #pragma unroll
        for (int k = 0; k < EPT; k++)
            idx[k] = (base + k < batch) ? idxs[base + k] : idxs[base];
    } else {
        idx[0] = idx[1] = idx[2] = idx[3] = 0;
    }

    const float k1 = __ldg(s_k1);
    const float b  = __ldg(s_b);
    const float bw = __ldg(s_bw);
    const float cA = bw * idf * (k1 + 1.0f);   // bm25*bw = cA*tf / den
    const float cD = k1 * (1.0f - b);
    const float cE = k1 * b;

    // ---------- wait for the sweep's writes ----------
    cudaGridDependencySynchronize();

    // sequential fr loads (coalesced, issued early)
    float4 frv = make_float4(0.f, 0.f, 0.f, 0.f);
    if (full) {
        frv = *reinterpret_cast<const float4*>(g_fr + base);
    } else if (base < batch) {
        float tmp[4];
        #pragma unroll
        for (int k = 0; k < EPT; k++)
            tmp[k] = (base + k < batch) ? g_fr[base + k] : 0.0f;
        frv = make_float4(tmp[0], tmp[1], tmp[2], tmp[3]);
    }
    float fr[EPT] = {frv.x, frv.y, frv.z, frv.w};

    // ---------- sequential L2 re-prime of the 8 MB table ----------
    {
        const uint2* pt = g_packed;
        for (int i = tid; i < n_docs; i += nthreads) {
            uint32_t dummy;
            asm volatile("ld.global.cg.u32 %0, [%1];"
                         : "=r"(dummy)
                         : "l"(reinterpret_cast<const char*>(pt) + (size_t)i * 8)
                         : "memory");
            (void)dummy;
        }
    }

    // ---------- deterministic per-block fold of col16 partials -> avg ----------
    __shared__ float sd[TPB];
    {
        float s = g_partials[t] + g_partials[t + 256]
                + g_partials[t + 512] + g_partials[t + 768];
        sd[t] = s;
        __syncthreads();
        for (int k = TPB / 2; k > 0; k >>= 1) {
            if (t < k) sd[t] += sd[t + k];
            __syncthreads();
        }
    }
    const float inv_avg = (float)n_docs / sd[0];   // 1/avg

    if (base >= batch) return;

    // ---------- random loads: L2 hits ----------
    uint2 p[EPT];
    #pragma unroll
    for (int k = 0; k < EPT; k++)
        p[k] = __ldg(&g_packed[idx[k]]);

    float res[EPT];
    #pragma unroll
    for (int k = 0; k < EPT; k++) {
        float PG = __uint_as_float(p[k].x);
        __nv_bfloat162 td = *reinterpret_cast<__nv_bfloat162*>(&p[k].y);
        float tf = __bfloat162float(td.x);
        float dl = __bfloat162float(td.y);
        float bm = cA * tf / (tf + cD + cE * dl * inv_avg);
        res[k] = PG + bm + fr[k];
    }

    if (full) {
        *reinterpret_cast<float4*>(out + base) =
            make_float4(res[0], res[1], res[2], res[3]);
    } else {
        #pragma unroll
        for (int k = 0; k < EPT; k++)
            if (base + k < batch) out[base + k] = res[k];
    }
}

// ---------------------------------------------------------------------------
extern "C" void kernel_launch(void* const* d_in, const int* in_sizes, int n_in,
                              void* d_out, int out_size)
{
    const int*   idxs = (const int*)d_in[0];
    const float* gf   = (const float*)d_in[1];
    const float* k1   = (const float*)d_in[2];
    const float* b    = (const float*)d_in[3];
    const float* bw   = (const float*)d_in[4];
    const float* prw  = (const float*)d_in[5];
    const float* inw  = (const float*)d_in[6];
    const float* outw = (const float*)d_in[7];
    const float* frw  = (const float*)d_in[8];
    float* out = (float*)d_out;

    int batch  = in_sizes[0];
    int n_docs = in_sizes[1] / N_FEAT;
    if (n_docs > MAX_DOCS) n_docs = MAX_DOCS;
    if (batch  > MAX_BATCH) batch = MAX_BATCH;

    // idf in the reference's exact f32 operation order (num == total):
    float total = (float)n_docs;
    float idf = logf(((total - total) + 0.5f) / (total + 0.5f) + 1.0f);

    sweep_kernel<<<SUM_BLOCKS, TPB>>>(gf, prw, inw, outw, frw, n_docs, batch);

    int gblocks = (batch + TPB * EPT - 1) / (TPB * EPT);

    cudaLaunchConfig_t cfg = {};
    cfg.gridDim  = dim3((unsigned)gblocks, 1, 1);
    cfg.blockDim = dim3(TPB, 1, 1);
    cfg.dynamicSmemBytes = 0;
    cfg.stream = 0;

    cudaLaunchAttribute attr[1];
    attr[0].id = cudaLaunchAttributeProgrammaticStreamSerialization;
    attr[0].val.programmaticStreamSerializationAllowed = 1;
    cfg.attrs = attr;
    cfg.numAttrs = 1;

    cudaLaunchKernelEx(&cfg, gather_kernel, idxs, k1, b, bw, out,
                       batch, n_docs, idf);
}